// round 2
// baseline (speedup 1.0000x reference)
#include <cuda_runtime.h>
#include <cstdint>

#define NN   10000
#define E0   320000
#define ET   330000
#define HIDD 256

// ---------------- scratch (device globals; no allocation allowed) ----------
__device__ __align__(256) float g_xl[NN * HIDD];
__device__ __align__(256) float g_xr[NN * HIDD];
__device__ __align__(256) float g_h[NN * HIDD];
__device__ __align__(256) float g_hres[NN * HIDD];
__device__ __align__(256) float g_agg[NN * HIDD];
__device__ __align__(256) float g_score[ET * 8];
__device__ __align__(256) float g_m[NN * 8];
__device__ __align__(256) float g_denom[NN * 8];
__device__ __align__(256) int   g_src[ET];
__device__ __align__(256) int   g_dst[ET];

// ---------------- edge list build: dtype auto-detect + self-loops ----------
// edge_index may be int32 (JAX default, x64 disabled) or int64. Detect by
// inspecting the first 16 logical elements interpreted as int64: if all are
// in [0, NN) (high word 0, low word valid), it is int64; otherwise int32.
__global__ void k_edges(const void* __restrict__ ei_raw,
                        int* __restrict__ src, int* __restrict__ dst) {
    int e = blockIdx.x * blockDim.x + threadIdx.x;
    if (e >= ET) return;

    const long long* e64 = (const long long*)ei_raw;
    const int*       e32 = (const int*)ei_raw;

    bool is64 = true;
#pragma unroll
    for (int i = 0; i < 16; i++) {
        long long v = e64[i];
        if (v < 0 || v >= NN) { is64 = false; break; }
    }

    int s, d;
    if (e < E0) {
        if (is64) {
            s = (int)e64[e];
            d = (int)e64[E0 + e];
        } else {
            s = e32[e];
            d = e32[E0 + e];
        }
    } else {
        s = e - E0;
        d = e - E0;
    }
    // hard guard against OOB (correctness still validated by rel_err)
    s = min(max(s, 0), NN - 1);
    d = min(max(d, 0), NN - 1);
    src[e] = s;
    dst[e] = d;
}

// ---------------- per-layer init: m=-inf, denom=0, agg=0 -------------------
__global__ void k_init(float* __restrict__ m, float* __restrict__ denom,
                       float* __restrict__ agg, int nh, int nagg) {
    int i = blockIdx.x * blockDim.x + threadIdx.x;
    if (i < nh) {
        m[i] = __int_as_float(0xff800000);  // -inf
        denom[i] = 0.0f;
    }
    if (i < nagg) agg[i] = 0.0f;
}

// ---------------- SGEMM: C[M,N] = A[M,K] @ B[K,N], row-major ---------------
// 64x64 block tile, BK=16, 256 threads, 4x4 micro-tile per thread.
// K is always a multiple of 16 here (128 or 256).
__global__ void k_gemm(const float* __restrict__ A, const float* __restrict__ B,
                       float* __restrict__ C, int M, int N, int K) {
    __shared__ __align__(16) float As[16][64];
    __shared__ __align__(16) float Bs[16][64];
    int tid = threadIdx.x;
    int tx = tid & 15, ty = tid >> 4;
    int m0 = blockIdx.y * 64, n0 = blockIdx.x * 64;

    float acc[4][4];
#pragma unroll
    for (int i = 0; i < 4; i++)
#pragma unroll
        for (int j = 0; j < 4; j++) acc[i][j] = 0.0f;

    for (int k0 = 0; k0 < K; k0 += 16) {
        // A tile: 64 rows x 16 k  (1 float4 per thread), stored transposed
        {
            int r = tid >> 2;               // 0..63 (row within tile)
            int kq = (tid & 3) * 4;         // 0,4,8,12
            int gm = m0 + r;
            float4 v = make_float4(0.f, 0.f, 0.f, 0.f);
            if (gm < M) v = *(const float4*)(A + (size_t)gm * K + k0 + kq);
            As[kq + 0][r] = v.x;
            As[kq + 1][r] = v.y;
            As[kq + 2][r] = v.z;
            As[kq + 3][r] = v.w;
        }
        // B tile: 16 k x 64 cols (1 float4 per thread)
        {
            int r = tid >> 4;               // 0..15 (k within tile)
            int cq = (tid & 15) * 4;        // 0..60
            int gn = n0 + cq;
            float4 v = make_float4(0.f, 0.f, 0.f, 0.f);
            if (gn + 3 < N) v = *(const float4*)(B + (size_t)(k0 + r) * N + gn);
            *(float4*)&Bs[r][cq] = v;
        }
        __syncthreads();
#pragma unroll
        for (int k = 0; k < 16; k++) {
            float4 a = *(const float4*)&As[k][ty * 4];
            float4 b = *(const float4*)&Bs[k][tx * 4];
            float ar[4] = {a.x, a.y, a.z, a.w};
            float br[4] = {b.x, b.y, b.z, b.w};
#pragma unroll
            for (int i = 0; i < 4; i++)
#pragma unroll
                for (int j = 0; j < 4; j++) acc[i][j] += ar[i] * br[j];
        }
        __syncthreads();
    }
#pragma unroll
    for (int i = 0; i < 4; i++) {
        int gm = m0 + ty * 4 + i;
        if (gm >= M) continue;
#pragma unroll
        for (int j = 0; j < 4; j++) {
            int gn = n0 + tx * 4 + j;
            if (gn < N) C[(size_t)gm * N + gn] = acc[i][j];
        }
    }
}

// ---------------- pass A: edge scores + segment max (atomic) ---------------
__device__ __forceinline__ void atomic_max_f32(float* addr, float v) {
    if (v >= 0.0f)
        atomicMax((int*)addr, __float_as_int(v));
    else
        atomicMin((unsigned int*)addr, __float_as_uint(v));
}

template <int H, int C>
__global__ void k_score(const float* __restrict__ xl, const float* __restrict__ xr,
                        const float* __restrict__ att,
                        const int* __restrict__ src, const int* __restrict__ dst,
                        float* __restrict__ score, float* __restrict__ m, int E) {
    int w = (int)((blockIdx.x * (unsigned)blockDim.x + threadIdx.x) >> 5);
    int lane = threadIdx.x & 31;
    if (w >= E) return;
    int s = src[w], d = dst[w];
    const float* xls = xl + (size_t)s * (H * C);
    const float* xrd = xr + (size_t)d * (H * C);
#pragma unroll
    for (int h = 0; h < H; h++) {
        float acc = 0.0f;
#pragma unroll
        for (int c = lane; c < C; c += 32) {
            float v = xls[h * C + c] + xrd[h * C + c];
            v = v > 0.0f ? v : 0.2f * v;
            acc += v * att[h * C + c];
        }
#pragma unroll
        for (int o = 16; o > 0; o >>= 1) acc += __shfl_xor_sync(0xffffffffu, acc, o);
        if (lane == 0) {
            score[(size_t)w * H + h] = acc;
            atomic_max_f32(m + (size_t)d * H + h, acc);
        }
    }
}

// ---------------- pass B: exp + segment sum ---------------------------------
template <int H>
__global__ void k_exp(const int* __restrict__ dst, float* __restrict__ score,
                      const float* __restrict__ m, float* __restrict__ denom, int E) {
    int t = blockIdx.x * blockDim.x + threadIdx.x;
    if (t >= E * H) return;
    int e = t / H;
    int h = t - e * H;
    int d = dst[e];
    float ex = __expf(score[t] - m[d * H + h]);
    score[t] = ex;
    atomicAdd(denom + d * H + h, ex);
}

// ---------------- pass C: weighted scatter (vector red) --------------------
__device__ __forceinline__ void red4(float* p, float x, float y, float z, float w) {
    asm volatile("red.global.add.v4.f32 [%0], {%1,%2,%3,%4};"
                 :: "l"(p), "f"(x), "f"(y), "f"(z), "f"(w) : "memory");
}

template <int H, int C>
__global__ void k_aggr(const float* __restrict__ xl, const float* __restrict__ score,
                       const float* __restrict__ denom,
                       const int* __restrict__ src, const int* __restrict__ dst,
                       float* __restrict__ agg, int E) {
    int w = (int)((blockIdx.x * (unsigned)blockDim.x + threadIdx.x) >> 5);
    int lane = threadIdx.x & 31;
    if (w >= E) return;
    int s = src[w], d = dst[w];
    const float4* xv = (const float4*)(xl + (size_t)s * (H * C));
    float* ab = agg + (size_t)d * (H * C);
#pragma unroll
    for (int idx = lane; idx < (H * C) / 4; idx += 32) {
        int h = (idx * 4) / C;
        float alpha = score[(size_t)w * H + h] / (denom[d * H + h] + 1e-16f);
        float4 v = xv[idx];
        red4(ab + idx * 4, alpha * v.x, alpha * v.y, alpha * v.z, alpha * v.w);
    }
}

// ---------------- epilogues -------------------------------------------------
__global__ void k_ep_relu(const float* __restrict__ agg, const float* __restrict__ b,
                          float* __restrict__ h, float* __restrict__ hres,
                          int total, int mask) {
    int i = blockIdx.x * blockDim.x + threadIdx.x;
    if (i >= total) return;
    float v = agg[i] + b[i & mask];
    v = v > 0.0f ? v : 0.0f;
    h[i] = v;
    hres[i] = v;
}

__global__ void k_ep_res(const float* __restrict__ agg, const float* __restrict__ b,
                         const float* __restrict__ hres, float* __restrict__ h,
                         int total, int mask) {
    int i = blockIdx.x * blockDim.x + threadIdx.x;
    if (i >= total) return;
    h[i] = agg[i] + b[i & mask] + hres[i];
}

__global__ void k_ep_out(const float* __restrict__ agg, const float* __restrict__ b,
                         float* __restrict__ out, int total, int mask) {
    int i = blockIdx.x * blockDim.x + threadIdx.x;
    if (i >= total) return;
    out[i] = agg[i] + b[i & mask];
}

// ---------------- launch ----------------------------------------------------
extern "C" void kernel_launch(void* const* d_in, const int* in_sizes, int n_in,
                              void* d_out, int out_size) {
    const float* x   = (const float*)d_in[0];
    const float* W1l = (const float*)d_in[1];
    const float* W1r = (const float*)d_in[2];
    const float* a1  = (const float*)d_in[3];
    const float* b1  = (const float*)d_in[4];
    const float* W2l = (const float*)d_in[5];
    const float* W2r = (const float*)d_in[6];
    const float* a2  = (const float*)d_in[7];
    const float* b2  = (const float*)d_in[8];
    const float* W3l = (const float*)d_in[9];
    const float* W3r = (const float*)d_in[10];
    const float* a3  = (const float*)d_in[11];
    const float* b3  = (const float*)d_in[12];
    const void*  ei  = (const void*)d_in[13];
    float* out = (float*)d_out;

    float *xl, *xr, *hh, *hres, *agg, *score, *mm, *dn;
    int *src, *dst;
    cudaGetSymbolAddress((void**)&xl, g_xl);
    cudaGetSymbolAddress((void**)&xr, g_xr);
    cudaGetSymbolAddress((void**)&hh, g_h);
    cudaGetSymbolAddress((void**)&hres, g_hres);
    cudaGetSymbolAddress((void**)&agg, g_agg);
    cudaGetSymbolAddress((void**)&score, g_score);
    cudaGetSymbolAddress((void**)&mm, g_m);
    cudaGetSymbolAddress((void**)&dn, g_denom);
    cudaGetSymbolAddress((void**)&src, g_src);
    cudaGetSymbolAddress((void**)&dst, g_dst);

    const int TB = 256;
    int eb  = (ET + TB - 1) / TB;              // per-edge, thread granularity
    int ewb = (ET * 32 + TB - 1) / TB;         // per-edge, warp granularity

    k_edges<<<eb, TB>>>(ei, src, dst);

    dim3 g256((256 + 63) / 64, (NN + 63) / 64);
    dim3 g32((32 + 63) / 64, (NN + 63) / 64);

    // ---------- layer 1 (Fin=128, H=8, C=32) ----------
    k_gemm<<<g256, TB>>>(x, W1l, xl, NN, 256, 128);
    k_gemm<<<g256, TB>>>(x, W1r, xr, NN, 256, 128);
    k_init<<<(NN * 256 + TB - 1) / TB, TB>>>(mm, dn, agg, NN * 8, NN * 256);
    k_score<8, 32><<<ewb, TB>>>(xl, xr, a1, src, dst, score, mm, ET);
    k_exp<8><<<(ET * 8 + TB - 1) / TB, TB>>>(dst, score, mm, dn, ET);
    k_aggr<8, 32><<<ewb, TB>>>(xl, score, dn, src, dst, agg, ET);
    k_ep_relu<<<(NN * 256 + TB - 1) / TB, TB>>>(agg, b1, hh, hres, NN * 256, 255);

    // ---------- layer 2 (Fin=256, H=8, C=32, residual) ----------
    k_gemm<<<g256, TB>>>(hh, W2l, xl, NN, 256, 256);
    k_gemm<<<g256, TB>>>(hh, W2r, xr, NN, 256, 256);
    k_init<<<(NN * 256 + TB - 1) / TB, TB>>>(mm, dn, agg, NN * 8, NN * 256);
    k_score<8, 32><<<ewb, TB>>>(xl, xr, a2, src, dst, score, mm, ET);
    k_exp<8><<<(ET * 8 + TB - 1) / TB, TB>>>(dst, score, mm, dn, ET);
    k_aggr<8, 32><<<ewb, TB>>>(xl, score, dn, src, dst, agg, ET);
    k_ep_res<<<(NN * 256 + TB - 1) / TB, TB>>>(agg, b2, hres, hh, NN * 256, 255);

    // ---------- layer 3 (Fin=256, H=1, C=32) ----------
    k_gemm<<<g32, TB>>>(hh, W3l, xl, NN, 32, 256);
    k_gemm<<<g32, TB>>>(hh, W3r, xr, NN, 32, 256);
    k_init<<<(NN * 32 + TB - 1) / TB, TB>>>(mm, dn, agg, NN * 1, NN * 32);
    k_score<1, 32><<<ewb, TB>>>(xl, xr, a3, src, dst, score, mm, ET);
    k_exp<1><<<eb, TB>>>(dst, score, mm, dn, ET);
    k_aggr<1, 32><<<ewb, TB>>>(xl, score, dn, src, dst, agg, ET);
    k_ep_out<<<(NN * 32 + TB - 1) / TB, TB>>>(agg, b3, out, NN * 32, 31);
}